// round 1
// baseline (speedup 1.0000x reference)
#include <cuda_runtime.h>

// ---------------------------------------------------------------------------
// Problem constants
// ---------------------------------------------------------------------------
#define BATCHN 16
#define SEQN   2048
#define MTOK   (BATCHN * SEQN)   // 32768 tokens
#define HID    512
#define ST     256
#define DINN   128
#define DOUTN  64
#define NLAYERS 4

#define NCHUNK 32
#define CLEN   64                // SEQN / NCHUNK

// GEMM tiling
#define BM 128
#define BN 64
#define BK 16

// ---------------------------------------------------------------------------
// Device scratch (no allocations allowed)
// ---------------------------------------------------------------------------
__device__ __align__(16) float g_h  [MTOK * HID];   // residual stream (64 MB)
__device__ __align__(16) float g_g  [MTOK * HID];   // gelu output      (64 MB)
__device__ __align__(16) float g_bur[MTOK * ST];    // Bu / h_state re  (32 MB)
__device__ __align__(16) float g_bui[MTOK * ST];    // Bu / h_state im  (32 MB)
__device__ __align__(16) float g_carry_re[NCHUNK * BATCHN * ST];
__device__ __align__(16) float g_carry_im[NCHUNK * BATCHN * ST];
__device__ __align__(16) float g_lam_re [ST];
__device__ __align__(16) float g_lam_im [ST];
__device__ __align__(16) float g_lamC_re[ST];
__device__ __align__(16) float g_lamC_im[ST];
__device__ __align__(16) float g_gam    [ST];

// ---------------------------------------------------------------------------
// Helpers
// ---------------------------------------------------------------------------
__device__ __forceinline__ float gelu_exact(float v) {
    return 0.5f * v * (1.0f + erff(v * 0.70710678118654752440f));
}
__device__ __forceinline__ float sigmoid_f(float v) {
    return 1.0f / (1.0f + expf(-v));
}

// ---------------------------------------------------------------------------
// Per-layer parameter prep: Lambda, Lambda^CLEN, gamma
// ---------------------------------------------------------------------------
__global__ void k_prep(const float* __restrict__ nu, const float* __restrict__ th,
                       const float* __restrict__ gl)
{
    int s = threadIdx.x;
    float ev  = expf(nu[s]);
    float et  = expf(th[s]);
    float mag = expf(-ev);
    g_lam_re[s] = mag * cosf(et);
    g_lam_im[s] = mag * sinf(et);
    const float c = (float)CLEN;
    float magC = expf(-c * ev);
    g_lamC_re[s] = magC * cosf(c * et);
    g_lamC_im[s] = magC * sinf(c * et);
    g_gam[s] = expf(gl[s]);
}

// ---------------------------------------------------------------------------
// GEMM 1: embedding.  g_h = x @ emb_W^T + emb_b   (K=128, N=512)
// ---------------------------------------------------------------------------
__global__ __launch_bounds__(256, 2)
void k_emb(const float* __restrict__ A, const float* __restrict__ W,
           const float* __restrict__ bias)
{
    const int K = DINN, N = HID;
    __shared__ __align__(16) float As[BK][BM];
    __shared__ __align__(16) float Ws[BK][BN];
    const int tid = threadIdx.x;
    const int m0 = blockIdx.y * BM, n0 = blockIdx.x * BN;
    const int ar = tid >> 2, ac = (tid & 3) << 2;
    const int ty = tid >> 4, tx = tid & 15;

    const float* Ap  = A + (size_t)(m0 + ar) * K + ac;
    const float* Ap2 = Ap + (size_t)64 * K;
    const float* Wp  = W + (size_t)(n0 + ar) * K + ac;

    float acc[8][4];
#pragma unroll
    for (int i = 0; i < 8; ++i)
#pragma unroll
        for (int j = 0; j < 4; ++j) acc[i][j] = 0.f;

    const int NKt = K / BK;
    float4 ra0 = *(const float4*)Ap;
    float4 ra1 = *(const float4*)Ap2;
    float4 rw0 = *(const float4*)Wp;

    for (int kt = 0; kt < NKt; ++kt) {
        As[ac+0][ar]    = ra0.x; As[ac+1][ar]    = ra0.y; As[ac+2][ar]    = ra0.z; As[ac+3][ar]    = ra0.w;
        As[ac+0][ar+64] = ra1.x; As[ac+1][ar+64] = ra1.y; As[ac+2][ar+64] = ra1.z; As[ac+3][ar+64] = ra1.w;
        Ws[ac+0][ar]    = rw0.x; Ws[ac+1][ar]    = rw0.y; Ws[ac+2][ar]    = rw0.z; Ws[ac+3][ar]    = rw0.w;
        __syncthreads();
        if (kt + 1 < NKt) {
            ra0 = *(const float4*)(Ap  + (kt+1)*BK);
            ra1 = *(const float4*)(Ap2 + (kt+1)*BK);
            rw0 = *(const float4*)(Wp  + (kt+1)*BK);
        }
#pragma unroll
        for (int k = 0; k < BK; ++k) {
            float4 a0 = *(const float4*)&As[k][ty*8];
            float4 a1 = *(const float4*)&As[k][ty*8+4];
            float4 bb = *(const float4*)&Ws[k][tx*4];
            float a[8] = {a0.x,a0.y,a0.z,a0.w,a1.x,a1.y,a1.z,a1.w};
            float b[4] = {bb.x,bb.y,bb.z,bb.w};
#pragma unroll
            for (int i = 0; i < 8; ++i)
#pragma unroll
                for (int j = 0; j < 4; ++j)
                    acc[i][j] = fmaf(a[i], b[j], acc[i][j]);
        }
        __syncthreads();
    }
    const int nco = n0 + tx*4;
    float4 bv = *(const float4*)&bias[nco];
#pragma unroll
    for (int i = 0; i < 8; ++i) {
        float4 o;
        o.x = acc[i][0] + bv.x; o.y = acc[i][1] + bv.y;
        o.z = acc[i][2] + bv.z; o.w = acc[i][3] + bv.w;
        *(float4*)&g_h[(size_t)(m0 + ty*8 + i) * N + nco] = o;
    }
}

// ---------------------------------------------------------------------------
// GEMM 2: Bu (dual weights, dual output, gamma scale)
// g_bur/g_bui = (g_h @ B_{re,im}^T) * gamma   (K=512, N=256)
// ---------------------------------------------------------------------------
__global__ __launch_bounds__(256)
void k_bu(const float* __restrict__ Wre, const float* __restrict__ Wim)
{
    const int K = HID, N = ST;
    __shared__ __align__(16) float As[BK][BM];
    __shared__ __align__(16) float Wr[BK][BN];
    __shared__ __align__(16) float Wi[BK][BN];
    const int tid = threadIdx.x;
    const int m0 = blockIdx.y * BM, n0 = blockIdx.x * BN;
    const int ar = tid >> 2, ac = (tid & 3) << 2;
    const int ty = tid >> 4, tx = tid & 15;

    const float* Ap  = g_h + (size_t)(m0 + ar) * K + ac;
    const float* Ap2 = Ap + (size_t)64 * K;
    const float* Wpr = Wre + (size_t)(n0 + ar) * K + ac;
    const float* Wpi = Wim + (size_t)(n0 + ar) * K + ac;

    float accR[8][4], accI[8][4];
#pragma unroll
    for (int i = 0; i < 8; ++i)
#pragma unroll
        for (int j = 0; j < 4; ++j) { accR[i][j] = 0.f; accI[i][j] = 0.f; }

    const int NKt = K / BK;
    float4 ra0 = *(const float4*)Ap;
    float4 ra1 = *(const float4*)Ap2;
    float4 rwr = *(const float4*)Wpr;
    float4 rwi = *(const float4*)Wpi;

    for (int kt = 0; kt < NKt; ++kt) {
        As[ac+0][ar]    = ra0.x; As[ac+1][ar]    = ra0.y; As[ac+2][ar]    = ra0.z; As[ac+3][ar]    = ra0.w;
        As[ac+0][ar+64] = ra1.x; As[ac+1][ar+64] = ra1.y; As[ac+2][ar+64] = ra1.z; As[ac+3][ar+64] = ra1.w;
        Wr[ac+0][ar] = rwr.x; Wr[ac+1][ar] = rwr.y; Wr[ac+2][ar] = rwr.z; Wr[ac+3][ar] = rwr.w;
        Wi[ac+0][ar] = rwi.x; Wi[ac+1][ar] = rwi.y; Wi[ac+2][ar] = rwi.z; Wi[ac+3][ar] = rwi.w;
        __syncthreads();
        if (kt + 1 < NKt) {
            ra0 = *(const float4*)(Ap  + (kt+1)*BK);
            ra1 = *(const float4*)(Ap2 + (kt+1)*BK);
            rwr = *(const float4*)(Wpr + (kt+1)*BK);
            rwi = *(const float4*)(Wpi + (kt+1)*BK);
        }
#pragma unroll
        for (int k = 0; k < BK; ++k) {
            float4 a0 = *(const float4*)&As[k][ty*8];
            float4 a1 = *(const float4*)&As[k][ty*8+4];
            float4 br = *(const float4*)&Wr[k][tx*4];
            float4 bi = *(const float4*)&Wi[k][tx*4];
            float a[8] = {a0.x,a0.y,a0.z,a0.w,a1.x,a1.y,a1.z,a1.w};
            float r[4] = {br.x,br.y,br.z,br.w};
            float m[4] = {bi.x,bi.y,bi.z,bi.w};
#pragma unroll
            for (int i = 0; i < 8; ++i)
#pragma unroll
                for (int j = 0; j < 4; ++j) {
                    accR[i][j] = fmaf(a[i], r[j], accR[i][j]);
                    accI[i][j] = fmaf(a[i], m[j], accI[i][j]);
                }
        }
        __syncthreads();
    }
    const int nco = n0 + tx*4;
    float4 gv = *(const float4*)&g_gam[nco];
    float gj[4] = {gv.x, gv.y, gv.z, gv.w};
#pragma unroll
    for (int i = 0; i < 8; ++i) {
        size_t row = (size_t)(m0 + ty*8 + i) * N + nco;
        float4 oR, oI;
        oR.x = accR[i][0]*gj[0]; oR.y = accR[i][1]*gj[1];
        oR.z = accR[i][2]*gj[2]; oR.w = accR[i][3]*gj[3];
        oI.x = accI[i][0]*gj[0]; oI.y = accI[i][1]*gj[1];
        oI.z = accI[i][2]*gj[2]; oI.w = accI[i][3]*gj[3];
        *(float4*)&g_bur[row] = oR;
        *(float4*)&g_bui[row] = oI;
    }
}

// ---------------------------------------------------------------------------
// Scan phase 1: local (per-chunk) scan, in place on g_bur/g_bui
// ---------------------------------------------------------------------------
__global__ void k_scan_local()
{
    const int b = blockIdx.y, j = blockIdx.x, s = threadIdx.x;
    const float lre = g_lam_re[s], lim = g_lam_im[s];
    float hre = 0.f, him = 0.f;
    size_t base = ((size_t)(b * SEQN + j * CLEN)) * ST + s;
#pragma unroll 4
    for (int t = 0; t < CLEN; ++t) {
        size_t idx = base + (size_t)t * ST;
        float br = g_bur[idx], bi = g_bui[idx];
        float nr = fmaf(lre, hre, fmaf(-lim, him, br));
        float ni = fmaf(lre, him, fmaf( lim, hre, bi));
        hre = nr; him = ni;
        g_bur[idx] = hre; g_bui[idx] = him;
    }
}

// ---------------------------------------------------------------------------
// Scan phase 2: carry sweep across chunks (Lambda^CLEN combine)
// ---------------------------------------------------------------------------
__global__ void k_scan_carry()
{
    const int b = blockIdx.x, s = threadIdx.x;
    const float lcre = g_lamC_re[s], lcim = g_lamC_im[s];
    float cre = 0.f, cim = 0.f;
#pragma unroll 8
    for (int j = 0; j < NCHUNK; ++j) {
        int cidx = (j * BATCHN + b) * ST + s;
        g_carry_re[cidx] = cre;
        g_carry_im[cidx] = cim;
        size_t eidx = ((size_t)(b * SEQN + j * CLEN + CLEN - 1)) * ST + s;
        float er = g_bur[eidx], ei = g_bui[eidx];
        float nr = fmaf(lcre, cre, fmaf(-lcim, cim, er));
        float ni = fmaf(lcre, cim, fmaf( lcim, cre, ei));
        cre = nr; cim = ni;
    }
}

// ---------------------------------------------------------------------------
// Scan phase 3: fixup  h_t += Lambda^{t+1} * carry
// ---------------------------------------------------------------------------
__global__ void k_scan_fix()
{
    const int b = blockIdx.y, j = blockIdx.x + 1, s = threadIdx.x;
    int cidx = (j * BATCHN + b) * ST + s;
    float cre = g_carry_re[cidx], cim = g_carry_im[cidx];
    const float lre = g_lam_re[s], lim = g_lam_im[s];
    float ccr = lre * cre - lim * cim;
    float cci = lre * cim + lim * cre;
    size_t base = ((size_t)(b * SEQN + j * CLEN)) * ST + s;
#pragma unroll 4
    for (int t = 0; t < CLEN; ++t) {
        size_t idx = base + (size_t)t * ST;
        g_bur[idx] += ccr;
        g_bui[idx] += cci;
        float nr = lre * ccr - lim * cci;
        float ni = lre * cci + lim * ccr;
        ccr = nr; cci = ni;
    }
}

// ---------------------------------------------------------------------------
// GEMM 3: C projection + D skip + exact GELU
// g_g = gelu(hs_re @ C_re^T - hs_im @ C_im^T + g_h * D)  (K=256, N=512)
// ---------------------------------------------------------------------------
__global__ __launch_bounds__(256, 2)
void k_cproj(const float* __restrict__ Cre, const float* __restrict__ Cim,
             const float* __restrict__ Dv)
{
    const int K = ST, N = HID;
    __shared__ __align__(16) float Ar[BK][BM];
    __shared__ __align__(16) float Ai[BK][BM];
    __shared__ __align__(16) float Wr[BK][BN];
    __shared__ __align__(16) float Wi[BK][BN];
    const int tid = threadIdx.x;
    const int m0 = blockIdx.y * BM, n0 = blockIdx.x * BN;
    const int ar = tid >> 2, ac = (tid & 3) << 2;
    const int ty = tid >> 4, tx = tid & 15;

    const float* Apr  = g_bur + (size_t)(m0 + ar) * K + ac;
    const float* Apr2 = Apr + (size_t)64 * K;
    const float* Api  = g_bui + (size_t)(m0 + ar) * K + ac;
    const float* Api2 = Api + (size_t)64 * K;
    const float* Wpr  = Cre + (size_t)(n0 + ar) * K + ac;
    const float* Wpi  = Cim + (size_t)(n0 + ar) * K + ac;

    float acc[8][4];
#pragma unroll
    for (int i = 0; i < 8; ++i)
#pragma unroll
        for (int j = 0; j < 4; ++j) acc[i][j] = 0.f;

    const int NKt = K / BK;
    float4 rr0 = *(const float4*)Apr;
    float4 rr1 = *(const float4*)Apr2;
    float4 ri0 = *(const float4*)Api;
    float4 ri1 = *(const float4*)Api2;
    float4 rwr = *(const float4*)Wpr;
    float4 rwi = *(const float4*)Wpi;

    for (int kt = 0; kt < NKt; ++kt) {
        Ar[ac+0][ar]    = rr0.x; Ar[ac+1][ar]    = rr0.y; Ar[ac+2][ar]    = rr0.z; Ar[ac+3][ar]    = rr0.w;
        Ar[ac+0][ar+64] = rr1.x; Ar[ac+1][ar+64] = rr1.y; Ar[ac+2][ar+64] = rr1.z; Ar[ac+3][ar+64] = rr1.w;
        Ai[ac+0][ar]    = ri0.x; Ai[ac+1][ar]    = ri0.y; Ai[ac+2][ar]    = ri0.z; Ai[ac+3][ar]    = ri0.w;
        Ai[ac+0][ar+64] = ri1.x; Ai[ac+1][ar+64] = ri1.y; Ai[ac+2][ar+64] = ri1.z; Ai[ac+3][ar+64] = ri1.w;
        Wr[ac+0][ar] = rwr.x; Wr[ac+1][ar] = rwr.y; Wr[ac+2][ar] = rwr.z; Wr[ac+3][ar] = rwr.w;
        Wi[ac+0][ar] = rwi.x; Wi[ac+1][ar] = rwi.y; Wi[ac+2][ar] = rwi.z; Wi[ac+3][ar] = rwi.w;
        __syncthreads();
        if (kt + 1 < NKt) {
            rr0 = *(const float4*)(Apr  + (kt+1)*BK);
            rr1 = *(const float4*)(Apr2 + (kt+1)*BK);
            ri0 = *(const float4*)(Api  + (kt+1)*BK);
            ri1 = *(const float4*)(Api2 + (kt+1)*BK);
            rwr = *(const float4*)(Wpr  + (kt+1)*BK);
            rwi = *(const float4*)(Wpi  + (kt+1)*BK);
        }
#pragma unroll
        for (int k = 0; k < BK; ++k) {
            float4 a0 = *(const float4*)&Ar[k][ty*8];
            float4 a1 = *(const float4*)&Ar[k][ty*8+4];
            float4 c0 = *(const float4*)&Ai[k][ty*8];
            float4 c1 = *(const float4*)&Ai[k][ty*8+4];
            float4 br = *(const float4*)&Wr[k][tx*4];
            float4 bi = *(const float4*)&Wi[k][tx*4];
            float aR[8] = {a0.x,a0.y,a0.z,a0.w,a1.x,a1.y,a1.z,a1.w};
            float aI[8] = {c0.x,c0.y,c0.z,c0.w,c1.x,c1.y,c1.z,c1.w};
            float wR[4] = {br.x,br.y,br.z,br.w};
            float wI[4] = {bi.x,bi.y,bi.z,bi.w};
#pragma unroll
            for (int i = 0; i < 8; ++i)
#pragma unroll
                for (int j = 0; j < 4; ++j) {
                    acc[i][j] = fmaf(aR[i],  wR[j], acc[i][j]);
                    acc[i][j] = fmaf(-aI[i], wI[j], acc[i][j]);
                }
        }
        __syncthreads();
    }
    const int nco = n0 + tx*4;
    float4 dv = *(const float4*)&Dv[nco];
    float dj[4] = {dv.x, dv.y, dv.z, dv.w};
#pragma unroll
    for (int i = 0; i < 8; ++i) {
        size_t row = (size_t)(m0 + ty*8 + i) * N + nco;
        float4 hv = *(const float4*)&g_h[row];
        float4 o;
        o.x = gelu_exact(acc[i][0] + hv.x * dj[0]);
        o.y = gelu_exact(acc[i][1] + hv.y * dj[1]);
        o.z = gelu_exact(acc[i][2] + hv.z * dj[2]);
        o.w = gelu_exact(acc[i][3] + hv.w * dj[3]);
        *(float4*)&g_g[row] = o;
    }
}

// ---------------------------------------------------------------------------
// GEMM 4: GLU + residual.  g_h += (g@W1^T+b1) * sigmoid(g@W2^T+b2)
// (K=512, N=512, dual accumulator)
// ---------------------------------------------------------------------------
__global__ __launch_bounds__(256)
void k_glu(const float* __restrict__ W1, const float* __restrict__ b1,
           const float* __restrict__ W2, const float* __restrict__ b2)
{
    const int K = HID, N = HID;
    __shared__ __align__(16) float As[BK][BM];
    __shared__ __align__(16) float Wa[BK][BN];
    __shared__ __align__(16) float Wb[BK][BN];
    const int tid = threadIdx.x;
    const int m0 = blockIdx.y * BM, n0 = blockIdx.x * BN;
    const int ar = tid >> 2, ac = (tid & 3) << 2;
    const int ty = tid >> 4, tx = tid & 15;

    const float* Ap  = g_g + (size_t)(m0 + ar) * K + ac;
    const float* Ap2 = Ap + (size_t)64 * K;
    const float* Wp1 = W1 + (size_t)(n0 + ar) * K + ac;
    const float* Wp2 = W2 + (size_t)(n0 + ar) * K + ac;

    float acc1[8][4], acc2[8][4];
#pragma unroll
    for (int i = 0; i < 8; ++i)
#pragma unroll
        for (int j = 0; j < 4; ++j) { acc1[i][j] = 0.f; acc2[i][j] = 0.f; }

    const int NKt = K / BK;
    float4 ra0 = *(const float4*)Ap;
    float4 ra1 = *(const float4*)Ap2;
    float4 rw1 = *(const float4*)Wp1;
    float4 rw2 = *(const float4*)Wp2;

    for (int kt = 0; kt < NKt; ++kt) {
        As[ac+0][ar]    = ra0.x; As[ac+1][ar]    = ra0.y; As[ac+2][ar]    = ra0.z; As[ac+3][ar]    = ra0.w;
        As[ac+0][ar+64] = ra1.x; As[ac+1][ar+64] = ra1.y; As[ac+2][ar+64] = ra1.z; As[ac+3][ar+64] = ra1.w;
        Wa[ac+0][ar] = rw1.x; Wa[ac+1][ar] = rw1.y; Wa[ac+2][ar] = rw1.z; Wa[ac+3][ar] = rw1.w;
        Wb[ac+0][ar] = rw2.x; Wb[ac+1][ar] = rw2.y; Wb[ac+2][ar] = rw2.z; Wb[ac+3][ar] = rw2.w;
        __syncthreads();
        if (kt + 1 < NKt) {
            ra0 = *(const float4*)(Ap  + (kt+1)*BK);
            ra1 = *(const float4*)(Ap2 + (kt+1)*BK);
            rw1 = *(const float4*)(Wp1 + (kt+1)*BK);
            rw2 = *(const float4*)(Wp2 + (kt+1)*BK);
        }
#pragma unroll
        for (int k = 0; k < BK; ++k) {
            float4 a0 = *(const float4*)&As[k][ty*8];
            float4 a1 = *(const float4*)&As[k][ty*8+4];
            float4 u  = *(const float4*)&Wa[k][tx*4];
            float4 v  = *(const float4*)&Wb[k][tx*4];
            float a[8] = {a0.x,a0.y,a0.z,a0.w,a1.x,a1.y,a1.z,a1.w};
            float w1r[4] = {u.x,u.y,u.z,u.w};
            float w2r[4] = {v.x,v.y,v.z,v.w};
#pragma unroll
            for (int i = 0; i < 8; ++i)
#pragma unroll
                for (int j = 0; j < 4; ++j) {
                    acc1[i][j] = fmaf(a[i], w1r[j], acc1[i][j]);
                    acc2[i][j] = fmaf(a[i], w2r[j], acc2[i][j]);
                }
        }
        __syncthreads();
    }
    const int nco = n0 + tx*4;
    float4 b1v = *(const float4*)&b1[nco];
    float4 b2v = *(const float4*)&b2[nco];
    float b1j[4] = {b1v.x, b1v.y, b1v.z, b1v.w};
    float b2j[4] = {b2v.x, b2v.y, b2v.z, b2v.w};
#pragma unroll
    for (int i = 0; i < 8; ++i) {
        size_t row = (size_t)(m0 + ty*8 + i) * N + nco;
        float4 hv = *(const float4*)&g_h[row];
        float hvv[4] = {hv.x, hv.y, hv.z, hv.w};
#pragma unroll
        for (int j = 0; j < 4; ++j) {
            float v1 = acc1[i][j] + b1j[j];
            float v2 = acc2[i][j] + b2j[j];
            hvv[j] += v1 * sigmoid_f(v2);
        }
        float4 o = {hvv[0], hvv[1], hvv[2], hvv[3]};
        *(float4*)&g_h[row] = o;
    }
}

// ---------------------------------------------------------------------------
// GEMM 5: output.  out = g_h @ out_W^T + out_b   (K=512, N=64)
// ---------------------------------------------------------------------------
__global__ __launch_bounds__(256, 2)
void k_out(const float* __restrict__ W, const float* __restrict__ bias,
           float* __restrict__ out)
{
    const int K = HID, N = DOUTN;
    __shared__ __align__(16) float As[BK][BM];
    __shared__ __align__(16) float Ws[BK][BN];
    const int tid = threadIdx.x;
    const int m0 = blockIdx.y * BM, n0 = blockIdx.x * BN;
    const int ar = tid >> 2, ac = (tid & 3) << 2;
    const int ty = tid >> 4, tx = tid & 15;

    const float* Ap  = g_h + (size_t)(m0 + ar) * K + ac;
    const float* Ap2 = Ap + (size_t)64 * K;
    const float* Wp  = W + (size_t)(n0 + ar) * K + ac;

    float acc[8][4];
#pragma unroll
    for (int i = 0; i < 8; ++i)
#pragma unroll
        for (int j = 0; j < 4; ++j) acc[i][j] = 0.f;

    const int NKt = K / BK;
    float4 ra0 = *(const float4*)Ap;
    float4 ra1 = *(const float4*)Ap2;
    float4 rw0 = *(const float4*)Wp;

    for (int kt = 0; kt < NKt; ++kt) {
        As[ac+0][ar]    = ra0.x; As[ac+1][ar]    = ra0.y; As[ac+2][ar]    = ra0.z; As[ac+3][ar]    = ra0.w;
        As[ac+0][ar+64] = ra1.x; As[ac+1][ar+64] = ra1.y; As[ac+2][ar+64] = ra1.z; As[ac+3][ar+64] = ra1.w;
        Ws[ac+0][ar]    = rw0.x; Ws[ac+1][ar]    = rw0.y; Ws[ac+2][ar]    = rw0.z; Ws[ac+3][ar]    = rw0.w;
        __syncthreads();
        if (kt + 1 < NKt) {
            ra0 = *(const float4*)(Ap  + (kt+1)*BK);
            ra1 = *(const float4*)(Ap2 + (kt+1)*BK);
            rw0 = *(const float4*)(Wp  + (kt+1)*BK);
        }
#pragma unroll
        for (int k = 0; k < BK; ++k) {
            float4 a0 = *(const float4*)&As[k][ty*8];
            float4 a1 = *(const float4*)&As[k][ty*8+4];
            float4 bb = *(const float4*)&Ws[k][tx*4];
            float a[8] = {a0.x,a0.y,a0.z,a0.w,a1.x,a1.y,a1.z,a1.w};
            float b[4] = {bb.x,bb.y,bb.z,bb.w};
#pragma unroll
            for (int i = 0; i < 8; ++i)
#pragma unroll
                for (int j = 0; j < 4; ++j)
                    acc[i][j] = fmaf(a[i], b[j], acc[i][j]);
        }
        __syncthreads();
    }
    const int nco = n0 + tx*4;
    float4 bv = *(const float4*)&bias[nco];
#pragma unroll
    for (int i = 0; i < 8; ++i) {
        float4 o;
        o.x = acc[i][0] + bv.x; o.y = acc[i][1] + bv.y;
        o.z = acc[i][2] + bv.z; o.w = acc[i][3] + bv.w;
        *(float4*)&out[(size_t)(m0 + ty*8 + i) * N + nco] = o;
    }
}

// ---------------------------------------------------------------------------
// Launch
// ---------------------------------------------------------------------------
extern "C" void kernel_launch(void* const* d_in, const int* in_sizes, int n_in,
                              void* d_out, int out_size)
{
    const float* x      = (const float*)d_in[0];
    const float* emb_W  = (const float*)d_in[1];
    const float* emb_b  = (const float*)d_in[2];
    const float* nu_log = (const float*)d_in[3];
    const float* th_log = (const float*)d_in[4];
    const float* gm_log = (const float*)d_in[5];
    const float* B_re   = (const float*)d_in[6];
    const float* B_im   = (const float*)d_in[7];
    const float* C_re   = (const float*)d_in[8];
    const float* C_im   = (const float*)d_in[9];
    const float* Dv     = (const float*)d_in[10];
    const float* W1     = (const float*)d_in[11];
    const float* b1     = (const float*)d_in[12];
    const float* W2     = (const float*)d_in[13];
    const float* b2     = (const float*)d_in[14];
    const float* out_W  = (const float*)d_in[15];
    const float* out_b  = (const float*)d_in[16];
    float* out = (float*)d_out;

    dim3 thr(256);
    k_emb<<<dim3(HID / BN, MTOK / BM), thr>>>(x, emb_W, emb_b);

    for (int l = 0; l < NLAYERS; ++l) {
        k_prep<<<1, ST>>>(nu_log + l * ST, th_log + l * ST, gm_log + l * ST);
        k_bu<<<dim3(ST / BN, MTOK / BM), thr>>>(B_re + (size_t)l * ST * HID,
                                                B_im + (size_t)l * ST * HID);
        k_scan_local<<<dim3(NCHUNK, BATCHN), ST>>>();
        k_scan_carry<<<BATCHN, ST>>>();
        k_scan_fix<<<dim3(NCHUNK - 1, BATCHN), ST>>>();
        k_cproj<<<dim3(HID / BN, MTOK / BM), thr>>>(C_re + (size_t)l * HID * ST,
                                                    C_im + (size_t)l * HID * ST,
                                                    Dv + l * HID);
        k_glu<<<dim3(HID / BN, MTOK / BM), thr>>>(W1 + (size_t)l * HID * HID, b1 + l * HID,
                                                  W2 + (size_t)l * HID * HID, b2 + l * HID);
    }
    k_out<<<dim3(DOUTN / BN, MTOK / BM), thr>>>(out_W, out_b, out);
}

// round 13
// speedup vs baseline: 2.2833x; 2.2833x over previous
#include <cuda_runtime.h>
#include <cuda_bf16.h>
#include <cstdint>

using bf16 = __nv_bfloat16;

#define BATCHN 16
#define SEQN   2048
#define MTOK   (BATCHN * SEQN)
#define HID    512
#define ST     256
#define DINN   128
#define DOUTN  64
#define NLAYERS 4
#define NCHUNK 64
#define CLEN   32

// ---------------- device scratch ----------------
__device__ __align__(1024) float g_h [MTOK * HID];
__device__ __align__(1024) float g_hs[MTOK * HID];        // [re(256)|im(256)]
__device__ __align__(1024) float g_t [MTOK * 2 * HID];
__device__ __align__(1024) bf16  g_h_hi[MTOK * HID], g_h_lo[MTOK * HID];
__device__ __align__(1024) bf16  g_s_hi[MTOK * HID], g_s_lo[MTOK * HID];
__device__ __align__(1024) bf16  g_g_hi[MTOK * HID], g_g_lo[MTOK * HID];
__device__ __align__(1024) bf16  g_x_hi[MTOK * DINN], g_x_lo[MTOK * DINN];
__device__ __align__(1024) bf16  g_w_hi[2 * HID * HID], g_w_lo[2 * HID * HID];
__device__ float g_car_re[NCHUNK * BATCHN * ST], g_car_im[NCHUNK * BATCHN * ST];
__device__ float g_lre[ST], g_lim[ST], g_lcre[ST], g_lcim[ST], g_gam[ST];

// ---------------- ptx helpers (sm_80-baseline only) ----------------
__device__ __forceinline__ uint32_t s2u(const void* p) {
    uint32_t a;
    asm("{ .reg .u64 t; cvta.to.shared.u64 t, %1; cvt.u32.u64 %0, t; }" : "=r"(a) : "l"(p));
    return a;
}
__device__ __forceinline__ void cp16(uint32_t dst, const void* src) {
    asm volatile("cp.async.cg.shared.global [%0], [%1], 16;" :: "r"(dst), "l"(src));
}
#define CP_COMMIT() asm volatile("cp.async.commit_group;" ::: "memory")
#define CP_WAIT1()  asm volatile("cp.async.wait_group 1;" ::: "memory")

__device__ __forceinline__ void ldm4(uint32_t* r, uint32_t addr) {
    asm volatile("ldmatrix.sync.aligned.m8n8.x4.shared.b16 {%0,%1,%2,%3}, [%4];"
        : "=r"(r[0]), "=r"(r[1]), "=r"(r[2]), "=r"(r[3]) : "r"(addr));
}
__device__ __forceinline__ void mma16816(float* c, const uint32_t* a, const uint32_t* b) {
    asm volatile("mma.sync.aligned.m16n8k16.row.col.f32.bf16.bf16.f32 "
        "{%0,%1,%2,%3}, {%4,%5,%6,%7}, {%8,%9}, {%0,%1,%2,%3};"
        : "+f"(c[0]), "+f"(c[1]), "+f"(c[2]), "+f"(c[3])
        : "r"(a[0]), "r"(a[1]), "r"(a[2]), "r"(a[3]), "r"(b[0]), "r"(b[1]));
}

// ---------------- math ----------------
__device__ __forceinline__ float gelu_exact(float v) {
    return 0.5f * v * (1.0f + erff(v * 0.70710678f));
}
__device__ __forceinline__ float sigmoid_f(float v) { return 1.0f / (1.0f + expf(-v)); }
__device__ __forceinline__ void split1(float x, bf16& h, bf16& l) {
    h = __float2bfloat16(x);
    l = __float2bfloat16(x - __bfloat162float(h));
}
__device__ __forceinline__ void wr4(bf16* H, bf16* L, size_t o, const float* v) {
    bf16 h0,l0,h1,l1,h2,l2,h3,l3;
    split1(v[0],h0,l0); split1(v[1],h1,l1); split1(v[2],h2,l2); split1(v[3],h3,l3);
    *(__nv_bfloat162*)(H+o)   = __halves2bfloat162(h0,h1);
    *(__nv_bfloat162*)(H+o+2) = __halves2bfloat162(h2,h3);
    *(__nv_bfloat162*)(L+o)   = __halves2bfloat162(l0,l1);
    *(__nv_bfloat162*)(L+o+2) = __halves2bfloat162(l2,l3);
}
__device__ __forceinline__ void wr2(bf16* H, bf16* L, size_t o, float v0, float v1) {
    bf16 h0,l0,h1,l1;
    split1(v0,h0,l0); split1(v1,h1,l1);
    *(__nv_bfloat162*)(H+o) = __halves2bfloat162(h0,h1);
    *(__nv_bfloat162*)(L+o) = __halves2bfloat162(l0,l1);
}

// ---------------- conversions ----------------
__global__ void k_cvt_x(const float* __restrict__ s, int n4) {
    int i = blockIdx.x * 256 + threadIdx.x;
    if (i >= n4) return;
    float4 v = ((const float4*)s)[i];
    float vv[4] = {v.x, v.y, v.z, v.w};
    wr4(g_x_hi, g_x_lo, (size_t)i * 4, vv);
}
__global__ void k_cvt_w(const float* __restrict__ s, int n4, int dstoff) {
    int i = blockIdx.x * 256 + threadIdx.x;
    if (i >= n4) return;
    float4 v = ((const float4*)s)[i];
    float vv[4] = {v.x, v.y, v.z, v.w};
    wr4(g_w_hi, g_w_lo, (size_t)dstoff + (size_t)i * 4, vv);
}
// strided: dst[r*dld + doff + c] = scale*src[r*scols + c]
__global__ void k_cvt_ws(const float* __restrict__ s, int n4, int scols4,
                         int dld, int doff, float scale) {
    int i = blockIdx.x * 256 + threadIdx.x;
    if (i >= n4) return;
    int r = i / scols4, c4 = i - r * scols4;
    float4 v = ((const float4*)s)[i];
    float vv[4] = {v.x*scale, v.y*scale, v.z*scale, v.w*scale};
    wr4(g_w_hi, g_w_lo, (size_t)r * dld + doff + c4 * 4, vv);
}

__global__ void k_prep(const float* __restrict__ nu, const float* __restrict__ th,
                       const float* __restrict__ gl) {
    int s = threadIdx.x;
    float ev = expf(nu[s]), et = expf(th[s]), mag = expf(-ev);
    g_lre[s] = mag * cosf(et); g_lim[s] = mag * sinf(et);
    float mc = expf(-(float)CLEN * ev);
    g_lcre[s] = mc * cosf((float)CLEN * et); g_lcim[s] = mc * sinf((float)CLEN * et);
    g_gam[s] = expf(gl[s]);
}

// ---------------------------------------------------------------------------
// Epilogue helper (writes a float pair at (row, col..col+1))
// EPI: 0=emb 1=Bu 2=cproj 3=raw(g_t) 4=out
// ---------------------------------------------------------------------------
template<int EPI>
__device__ __forceinline__ void epi2(float a0, float a1, int row, int col, int N,
                                     const float* __restrict__ ev,
                                     float* __restrict__ outp)
{
    size_t ob = (size_t)row * N + col;
    if constexpr (EPI == 0) {
        float v0 = a0 + ev[col], v1 = a1 + ev[col + 1];
        float2 o = {v0, v1};
        *(float2*)&g_h[ob] = o;
        wr2(g_h_hi, g_h_lo, ob, v0, v1);
    } else if constexpr (EPI == 1) {
        float v0 = a0 * g_gam[col & (ST - 1)];
        float v1 = a1 * g_gam[(col + 1) & (ST - 1)];
        float2 o = {v0, v1};
        *(float2*)&g_hs[ob] = o;
    } else if constexpr (EPI == 2) {
        float2 hv = *(const float2*)&g_h[ob];
        float v0 = gelu_exact(a0 + hv.x * ev[col]);
        float v1 = gelu_exact(a1 + hv.y * ev[col + 1]);
        wr2(g_g_hi, g_g_lo, ob, v0, v1);
    } else if constexpr (EPI == 3) {
        float2 o = {a0, a1};
        *(float2*)&g_t[ob] = o;
    } else {
        float2 o = {a0 + ev[col], a1 + ev[col + 1]};
        *(float2*)&outp[ob] = o;
    }
}

// ---------------------------------------------------------------------------
// split-bf16 GEMM on mma.sync (HMMA). out[M,N] = A[M,K] @ W[N,K]^T + epilogue
// CTA tile 128 x BN x 32, cp.async double buffer, ldmatrix fragments.
// AS: 0=x 1=h 2=s 3=g
// ---------------------------------------------------------------------------
template<int BN, int EPI, int AS>
__global__ __launch_bounds__(256) void
k_mma(int K, int N, const float* __restrict__ ev, float* __restrict__ outp)
{
    constexpr int LDA = 40;                    // padded bf16 row stride (80B)
    constexpr int A_BYTES = 128 * LDA * 2;     // 10240 per hi/lo buffer
    constexpr int W_BYTES = BN * LDA * 2;
    constexpr int STAGE = 2 * A_BYTES + 2 * W_BYTES;
    constexpr int WARP_M = (BN == 128) ? 2 : 4;
    constexpr int WARP_N = 8 / WARP_M;
    constexpr int TM = 128 / WARP_M;
    constexpr int TN = BN / WARP_N;
    constexpr int MT = TM / 16;
    constexpr int NT8 = TN / 8;

    extern __shared__ char sm[];
    const int tid = threadIdx.x, wid = tid >> 5, lane = tid & 31;
    const int m0 = blockIdx.y * 128, n0 = blockIdx.x * BN;
    const int wm = wid / WARP_N, wn = wid % WARP_N;

    const bf16 *Abh, *Abl;
    if constexpr (AS == 0)      { Abh = g_x_hi; Abl = g_x_lo; }
    else if constexpr (AS == 1) { Abh = g_h_hi; Abl = g_h_lo; }
    else if constexpr (AS == 2) { Abh = g_s_hi; Abl = g_s_lo; }
    else                        { Abh = g_g_hi; Abl = g_g_lo; }
    Abh += (size_t)m0 * K; Abl += (size_t)m0 * K;
    const bf16* Wbh = g_w_hi + (size_t)n0 * K;
    const bf16* Wbl = g_w_lo + (size_t)n0 * K;

    float acc[MT][NT8][4];
#pragma unroll
    for (int mt = 0; mt < MT; ++mt)
#pragma unroll
        for (int nt = 0; nt < NT8; ++nt)
#pragma unroll
            for (int j = 0; j < 4; ++j) acc[mt][nt][j] = 0.f;

    const uint32_t smBase = s2u(sm);
    const int nc = K >> 5;   // BK = 32

    // fill chunk c into stage s (cp.async, 16B granules)
    auto fill = [&](int c, int s) {
        const int co = c << 5;
        uint32_t ah = smBase + s * STAGE;
        uint32_t al = ah + A_BYTES;
        uint32_t wh = al + A_BYTES;
        uint32_t wl = wh + W_BYTES;
#pragma unroll
        for (int k = 0; k < 2; ++k) {          // A: 512 granules / 256 thr
            int i = tid + k * 256;
            int r = i >> 2, sec = i & 3;
            uint32_t d = (uint32_t)(r * (LDA * 2) + sec * 16);
            size_t go = (size_t)r * K + co + sec * 8;
            cp16(ah + d, Abh + go);
            cp16(al + d, Abl + go);
        }
#pragma unroll
        for (int k = 0; k < BN * 4 / 256; ++k) {
            int i = tid + k * 256;
            int r = i >> 2, sec = i & 3;
            uint32_t d = (uint32_t)(r * (LDA * 2) + sec * 16);
            size_t go = (size_t)r * K + co + sec * 8;
            cp16(wh + d, Wbh + go);
            cp16(wl + d, Wbl + go);
        }
    };

    fill(0, 0);
    CP_COMMIT();

    for (int c = 0; c < nc; ++c) {
        if (c + 1 < nc) fill(c + 1, (c + 1) & 1);
        CP_COMMIT();
        CP_WAIT1();
        __syncthreads();

        const int s = c & 1;
        uint32_t aBh = smBase + s * STAGE;
        uint32_t aBl = aBh + A_BYTES;
        uint32_t wBh = aBl + A_BYTES;
        uint32_t wBl = wBh + W_BYTES;

        // ldmatrix lane offsets
        const int arow = (lane & 7) + ((lane >> 3) & 1) * 8;   // A: row within 16
        const int acol = (lane >> 4) * 8;                      // A: col half
        const int brow = (lane & 7) + (lane >> 4) * 8;         // W: row within 16
        const int bcol = ((lane >> 3) & 1) * 8;                // W: col half

#pragma unroll
        for (int ks = 0; ks < 2; ++ks) {
            const int k0 = ks * 16;
            uint32_t ah[MT][4], al[MT][4];
#pragma unroll
            for (int mt = 0; mt < MT; ++mt) {
                uint32_t off = (uint32_t)(((wm * TM + mt * 16 + arow) * LDA + k0 + acol) * 2);
                ldm4(ah[mt], aBh + off);
                ldm4(al[mt], aBl + off);
            }
            uint32_t bh[NT8][2], bl[NT8][2];
#pragma unroll
            for (int np = 0; np < NT8 / 2; ++np) {
                uint32_t off = (uint32_t)(((wn * TN + np * 16 + brow) * LDA + k0 + bcol) * 2);
                uint32_t r4[4];
                ldm4(r4, wBh + off);
                bh[np*2][0] = r4[0]; bh[np*2][1] = r4[1];
                bh[np*2+1][0] = r4[2]; bh[np*2+1][1] = r4[3];
                ldm4(r4, wBl + off);
                bl[np*2][0] = r4[0]; bl[np*2][1] = r4[1];
                bl[np*2+1][0] = r4[2]; bl[np*2+1][1] = r4[3];
            }
#pragma unroll
            for (int mt = 0; mt < MT; ++mt)
#pragma unroll
                for (int nt = 0; nt < NT8; ++nt) {
                    mma16816(acc[mt][nt], ah[mt], bh[nt]);
                    mma16816(acc[mt][nt], ah[mt], bl[nt]);
                    mma16816(acc[mt][nt], al[mt], bh[nt]);
                }
        }
        __syncthreads();
    }

    // epilogue straight from registers
    const int qr = lane >> 2, qc = (lane & 3) * 2;
#pragma unroll
    for (int mt = 0; mt < MT; ++mt)
#pragma unroll
        for (int nt = 0; nt < NT8; ++nt) {
            int row = m0 + wm * TM + mt * 16 + qr;
            int col = n0 + wn * TN + nt * 8 + qc;
            epi2<EPI>(acc[mt][nt][0], acc[mt][nt][1], row,     col, N, ev, outp);
            epi2<EPI>(acc[mt][nt][2], acc[mt][nt][3], row + 8, col, N, ev, outp);
        }
}

// ---------------- scan (fp32, interleaved layout) ----------------
__global__ void k_scan_local() {
    const int b = blockIdx.y, j = blockIdx.x, s = threadIdx.x;
    const float lre = g_lre[s], lim = g_lim[s];
    float hr = 0.f, hi = 0.f;
    size_t base = ((size_t)(b * SEQN + j * CLEN)) * HID + s;
#pragma unroll 4
    for (int t = 0; t < CLEN; ++t) {
        size_t ix = base + (size_t)t * HID;
        float br = g_hs[ix], bi = g_hs[ix + ST];
        float nr = fmaf(lre, hr, fmaf(-lim, hi, br));
        float ni = fmaf(lre, hi, fmaf( lim, hr, bi));
        hr = nr; hi = ni;
        g_hs[ix] = hr; g_hs[ix + ST] = hi;
    }
}
__global__ void k_scan_carry() {
    const int b = blockIdx.x, s = threadIdx.x;
    const float lcre = g_lcre[s], lcim = g_lcim[s];
    float cr = 0.f, ci = 0.f;
#pragma unroll 8
    for (int j = 0; j < NCHUNK; ++j) {
        int ci2 = (j * BATCHN + b) * ST + s;
        g_car_re[ci2] = cr; g_car_im[ci2] = ci;
        size_t e = ((size_t)(b * SEQN + j * CLEN + CLEN - 1)) * HID + s;
        float er = g_hs[e], ei = g_hs[e + ST];
        float nr = fmaf(lcre, cr, fmaf(-lcim, ci, er));
        float ni = fmaf(lcre, ci, fmaf( lcim, cr, ei));
        cr = nr; ci = ni;
    }
}
__global__ void k_scan_fix() {
    const int b = blockIdx.y, j = blockIdx.x, s = threadIdx.x;
    int ci2 = (j * BATCHN + b) * ST + s;
    float cr = g_car_re[ci2], ci = g_car_im[ci2];
    const float lre = g_lre[s], lim = g_lim[s];
    float ar = lre * cr - lim * ci;
    float ai = lre * ci + lim * cr;
    size_t base = ((size_t)(b * SEQN + j * CLEN)) * HID + s;
#pragma unroll 4
    for (int t = 0; t < CLEN; ++t) {
        size_t ix = base + (size_t)t * HID;
        float vr = g_hs[ix] + ar;
        float vi = g_hs[ix + ST] + ai;
        bf16 h, l;
        split1(vr, h, l); g_s_hi[ix] = h;      g_s_lo[ix] = l;
        split1(vi, h, l); g_s_hi[ix + ST] = h; g_s_lo[ix + ST] = l;
        float nr = lre * ar - lim * ai;
        float ni = lre * ai + lim * ar;
        ar = nr; ai = ni;
    }
}

// ---------------- GLU combine ----------------
__global__ void k_glu_comb(const float* __restrict__ b1, const float* __restrict__ b2) {
    int i = blockIdx.x * 256 + threadIdx.x;
    if (i >= MTOK * HID / 4) return;
    int r = i >> 7, c4 = i & 127;
    float4 h  = ((float4*)g_h)[i];
    float4 t1 = *(const float4*)(g_t + (size_t)r * (2 * HID) + c4 * 4);
    float4 t2 = *(const float4*)(g_t + (size_t)r * (2 * HID) + HID + c4 * 4);
    float4 u1 = ((const float4*)b1)[c4];
    float4 u2 = ((const float4*)b2)[c4];
    float v[4];
    v[0] = h.x + (t1.x + u1.x) * sigmoid_f(t2.x + u2.x);
    v[1] = h.y + (t1.y + u1.y) * sigmoid_f(t2.y + u2.y);
    v[2] = h.z + (t1.z + u1.z) * sigmoid_f(t2.z + u2.z);
    v[3] = h.w + (t1.w + u1.w) * sigmoid_f(t2.w + u2.w);
    float4 o = {v[0], v[1], v[2], v[3]};
    ((float4*)g_h)[i] = o;
    wr4(g_h_hi, g_h_lo, (size_t)i * 4, v);
}

// ---------------- launch ----------------
extern "C" void kernel_launch(void* const* d_in, const int* in_sizes, int n_in,
                              void* d_out, int out_size)
{
    const float* x      = (const float*)d_in[0];
    const float* emb_W  = (const float*)d_in[1];
    const float* emb_b  = (const float*)d_in[2];
    const float* nu_log = (const float*)d_in[3];
    const float* th_log = (const float*)d_in[4];
    const float* gm_log = (const float*)d_in[5];
    const float* B_re   = (const float*)d_in[6];
    const float* B_im   = (const float*)d_in[7];
    const float* C_re   = (const float*)d_in[8];
    const float* C_im   = (const float*)d_in[9];
    const float* Dv     = (const float*)d_in[10];
    const float* W1     = (const float*)d_in[11];
    const float* b1     = (const float*)d_in[12];
    const float* W2     = (const float*)d_in[13];
    const float* b2     = (const float*)d_in[14];
    const float* out_W  = (const float*)d_in[15];
    const float* out_b  = (const float*)d_in[16];
    float* out = (float*)d_out;

    // smem: 2 stages of (2*A + 2*W) with LDA=40
    const int SM128 = 2 * (2 * 128 * 40 * 2 + 2 * 128 * 40 * 2);   // 81920
    const int SM64  = 2 * (2 * 128 * 40 * 2 + 2 * 64 * 40 * 2);    // 61440
    cudaFuncSetAttribute(k_mma<128,0,0>, cudaFuncAttributeMaxDynamicSharedMemorySize, SM128);
    cudaFuncSetAttribute(k_mma<128,1,1>, cudaFuncAttributeMaxDynamicSharedMemorySize, SM128);
    cudaFuncSetAttribute(k_mma<128,2,2>, cudaFuncAttributeMaxDynamicSharedMemorySize, SM128);
    cudaFuncSetAttribute(k_mma<128,3,3>, cudaFuncAttributeMaxDynamicSharedMemorySize, SM128);
    cudaFuncSetAttribute(k_mma<64,4,1>,  cudaFuncAttributeMaxDynamicSharedMemorySize, SM64);

    dim3 thr(256);
    // embedding
    k_cvt_x<<<MTOK * DINN / 1024, thr>>>(x, MTOK * DINN / 4);
    k_cvt_w<<<HID * DINN / 1024, thr>>>(emb_W, HID * DINN / 4, 0);
    k_mma<128,0,0><<<dim3(HID/128, MTOK/128), thr, SM128>>>(DINN, HID, emb_b, nullptr);

    for (int l = 0; l < NLAYERS; ++l) {
        k_prep<<<1, ST>>>(nu_log + l*ST, th_log + l*ST, gm_log + l*ST);
        // Bu: W' = [B_re ; B_im]  (N=512, K=512)
        k_cvt_w<<<ST * HID / 1024, thr>>>(B_re + (size_t)l*ST*HID, ST*HID/4, 0);
        k_cvt_w<<<ST * HID / 1024, thr>>>(B_im + (size_t)l*ST*HID, ST*HID/4, ST*HID);
        k_mma<128,1,1><<<dim3(HID/128, MTOK/128), thr, SM128>>>(HID, HID, nullptr, nullptr);
        // scan
        k_scan_local<<<dim3(NCHUNK, BATCHN), ST>>>();
        k_scan_carry<<<BATCHN, ST>>>();
        k_scan_fix<<<dim3(NCHUNK, BATCHN), ST>>>();
        // cproj: W' = [C_re | -C_im] along K (N=512, K=512)
        k_cvt_ws<<<HID * ST / 1024, thr>>>(C_re + (size_t)l*HID*ST, HID*ST/4, ST/4, HID, 0,  1.f);
        k_cvt_ws<<<HID * ST / 1024, thr>>>(C_im + (size_t)l*HID*ST, HID*ST/4, ST/4, HID, ST, -1.f);
        k_mma<128,2,2><<<dim3(HID/128, MTOK/128), thr, SM128>>>(HID, HID, Dv + l*HID, nullptr);
        // GLU: W' = [W1 ; W2]  (N=1024, K=512)
        k_cvt_w<<<HID * HID / 1024, thr>>>(W1 + (size_t)l*HID*HID, HID*HID/4, 0);
        k_cvt_w<<<HID * HID / 1024, thr>>>(W2 + (size_t)l*HID*HID, HID*HID/4, HID*HID);
        k_mma<128,3,3><<<dim3(2*HID/128, MTOK/128), thr, SM128>>>(HID, 2*HID, nullptr, nullptr);
        k_glu_comb<<<MTOK * HID / 1024, thr>>>(b1 + l*HID, b2 + l*HID);
    }
    // output: N=64, K=512
    k_cvt_w<<<DOUTN * HID / 1024, thr>>>(out_W, DOUTN*HID/4, 0);
    k_mma<64,4,1><<<dim3(1, MTOK/128), thr, SM64>>>(HID, DOUTN, out_b, out);
}